// round 2
// baseline (speedup 1.0000x reference)
#include <cuda_runtime.h>
#include <math.h>

#define BATCH 8
#define SEQ   4096
#define DIM   1024
#define NROWS (BATCH*SEQ)

// ---- scratch (static device globals: allocation-free) ----
__device__ float g_Q  [(size_t)NROWS*DIM];
__device__ float g_K  [(size_t)NROWS*DIM];
__device__ float g_V  [(size_t)NROWS*DIM];   // reused as ctx after KV is built
__device__ float g_KV [(size_t)BATCH*DIM*DIM];
__device__ float g_Ksum[BATCH*DIM];
__device__ float g_Z  [NROWS];

enum { EPI_NONE=0, EPI_BIAS=1, EPI_BIAS_ELU=2, EPI_DIVZ=3 };

// C[m,n] = sum_k A(m,k)*B(k,n)
// TA=0: A stored [M,K] (A[m*lda+k]);  TA=1: A stored [K,M] (A[k*lda+m])
// TB=0: B stored [K,N] (B[k*ldb+n]);  TB=1: B stored [N,K] (B[n*ldb+k])
// 128x128 tile, BK=8, 256 threads, 8x8 per-thread micro-tile, double-buffered smem.
template<int TA, int TB, int EPI>
__global__ __launch_bounds__(256, 2)
void gemm128(const float* __restrict__ A, const float* __restrict__ B,
             float* __restrict__ C, int lda, int ldb, int ldc, int K,
             const float* __restrict__ bias, const float* __restrict__ Zv,
             size_t sA, size_t sB, size_t sC, size_t sZ)
{
    __shared__ float As[2][8][128];
    __shared__ float Bs[2][8][128];

    const int tid  = threadIdx.x;
    const int rowg = tid >> 4;   // 0..15
    const int colg = tid & 15;   // 0..15
    const int m0 = blockIdx.y * 128;
    const int n0 = blockIdx.x * 128;

    A += (size_t)blockIdx.z * sA;
    B += (size_t)blockIdx.z * sB;
    C += (size_t)blockIdx.z * sC;

    // per-thread load coordinates
    int am, ak, bn, bk;
    if (TA == 0) { am = tid >> 1; ak = (tid & 1) * 4; }
    else         { ak = tid >> 5; am = (tid & 31) * 4; }
    if (TB == 0) { bk = tid >> 5; bn = (tid & 31) * 4; }
    else         { bn = tid >> 1; bk = (tid & 1) * 4; }

    float4 aReg, bReg;

    auto loadG = [&](int k0) {
        const float* ap = (TA == 0) ? &A[(size_t)(m0 + am) * lda + (k0 + ak)]
                                    : &A[(size_t)(k0 + ak) * lda + (m0 + am)];
        const float* bp = (TB == 0) ? &B[(size_t)(k0 + bk) * ldb + (n0 + bn)]
                                    : &B[(size_t)(n0 + bn) * ldb + (k0 + bk)];
        aReg = *(const float4*)ap;
        bReg = *(const float4*)bp;
    };
    auto storeS = [&](int buf) {
        if (TA == 0) {
            As[buf][ak+0][am] = aReg.x; As[buf][ak+1][am] = aReg.y;
            As[buf][ak+2][am] = aReg.z; As[buf][ak+3][am] = aReg.w;
        } else {
            *(float4*)&As[buf][ak][am] = aReg;
        }
        if (TB == 0) {
            *(float4*)&Bs[buf][bk][bn] = bReg;
        } else {
            Bs[buf][bk+0][bn] = bReg.x; Bs[buf][bk+1][bn] = bReg.y;
            Bs[buf][bk+2][bn] = bReg.z; Bs[buf][bk+3][bn] = bReg.w;
        }
    };

    float acc[8][8];
    #pragma unroll
    for (int i = 0; i < 8; i++)
        #pragma unroll
        for (int j = 0; j < 8; j++) acc[i][j] = 0.0f;

    const int nT = K / 8;
    loadG(0);
    storeS(0);
    __syncthreads();

    for (int t = 0; t < nT; t++) {
        const int cur = t & 1;
        if (t + 1 < nT) loadG((t + 1) * 8);

        #pragma unroll
        for (int kk = 0; kk < 8; kk++) {
            float a[8], b[8];
            *(float4*)(a)     = *(const float4*)&As[cur][kk][rowg * 8];
            *(float4*)(a + 4) = *(const float4*)&As[cur][kk][rowg * 8 + 4];
            *(float4*)(b)     = *(const float4*)&Bs[cur][kk][colg * 8];
            *(float4*)(b + 4) = *(const float4*)&Bs[cur][kk][colg * 8 + 4];
            #pragma unroll
            for (int i = 0; i < 8; i++)
                #pragma unroll
                for (int j = 0; j < 8; j++)
                    acc[i][j] += a[i] * b[j];
        }
        if (t + 1 < nT) {
            storeS(cur ^ 1);
            __syncthreads();
        }
    }

    // epilogue
    const float* Zp = (EPI == EPI_DIVZ) ? (Zv + blockIdx.z * sZ) : nullptr;
    #pragma unroll
    for (int i = 0; i < 8; i++) {
        const int m = m0 + rowg * 8 + i;
        const float zinv = (EPI == EPI_DIVZ) ? (1.0f / Zp[m]) : 1.0f;
        #pragma unroll
        for (int j = 0; j < 8; j++) {
            const int n = n0 + colg * 8 + j;
            float v = acc[i][j];
            if (EPI == EPI_BIAS || EPI == EPI_BIAS_ELU) v += bias[n];
            if (EPI == EPI_BIAS_ELU) v = (v > 0.0f) ? (v + 1.0f) : expf(v);
            if (EPI == EPI_DIVZ) v *= zinv;
            C[(size_t)m * ldc + n] = v;
        }
    }
}

// Ksum[b,d] = sum_n K[b,n,d] + 1e-6
__global__ void ksum_kernel(const float* __restrict__ K, float* __restrict__ Ks)
{
    const int d = blockIdx.x * blockDim.x + threadIdx.x;
    const int b = blockIdx.y;
    const float* p = K + (size_t)b * SEQ * DIM + d;
    float s = 0.0f;
    #pragma unroll 4
    for (int n = 0; n < SEQ; n++) s += p[(size_t)n * DIM];
    Ks[b * DIM + d] = s + 1e-6f;
}

// Z[row] = dot(Q[row,:], Ksum[b,:]) ; one warp per row
__global__ void z_kernel(const float* __restrict__ Q, const float* __restrict__ Ks,
                         float* __restrict__ Z)
{
    const int warp = threadIdx.x >> 5;
    const int lane = threadIdx.x & 31;
    const int row  = blockIdx.x * 8 + warp;
    const int b    = row >> 12;   // SEQ = 4096
    const float4* q  = (const float4*)(Q + (size_t)row * DIM);
    const float4* ks = (const float4*)(Ks + b * DIM);
    float s = 0.0f;
    for (int i = lane; i < DIM / 4; i += 32) {
        float4 a = q[i], c = ks[i];
        s += a.x * c.x + a.y * c.y + a.z * c.z + a.w * c.w;
    }
    #pragma unroll
    for (int o = 16; o; o >>= 1) s += __shfl_xor_sync(0xFFFFFFFFu, s, o);
    if (lane == 0) Z[row] = s;
}

extern "C" void kernel_launch(void* const* d_in, const int* in_sizes, int n_in,
                              void* d_out, int out_size)
{
    const float* x  = (const float*)d_in[0];
    const float* Wq = (const float*)d_in[1];
    const float* bq = (const float*)d_in[2];
    const float* Wk = (const float*)d_in[3];
    const float* bk = (const float*)d_in[4];
    const float* Wv = (const float*)d_in[5];
    const float* bv = (const float*)d_in[6];
    const float* Wo = (const float*)d_in[7];
    const float* bo = (const float*)d_in[8];

    float *Q, *K, *V, *KV, *KS, *Z;
    cudaGetSymbolAddress((void**)&Q,  g_Q);
    cudaGetSymbolAddress((void**)&K,  g_K);
    cudaGetSymbolAddress((void**)&V,  g_V);
    cudaGetSymbolAddress((void**)&KV, g_KV);
    cudaGetSymbolAddress((void**)&KS, g_Ksum);
    cudaGetSymbolAddress((void**)&Z,  g_Z);
    float* CTX = V;   // V is dead after the KV GEMM; reuse as ctx

    const dim3 thr(256);
    const dim3 gProj(DIM / 128, NROWS / 128, 1);

    // Q = elu(x Wq^T + bq)+1 ; K likewise ; V = x Wv^T + bv
    gemm128<0,1,EPI_BIAS_ELU><<<gProj, thr>>>(x, Wq, Q, DIM, DIM, DIM, DIM, bq, nullptr, 0,0,0,0);
    gemm128<0,1,EPI_BIAS_ELU><<<gProj, thr>>>(x, Wk, K, DIM, DIM, DIM, DIM, bk, nullptr, 0,0,0,0);
    gemm128<0,1,EPI_BIAS    ><<<gProj, thr>>>(x, Wv, V, DIM, DIM, DIM, DIM, bv, nullptr, 0,0,0,0);

    ksum_kernel<<<dim3(DIM / 256, BATCH), 256>>>(K, KS);
    z_kernel<<<NROWS / 8, 256>>>(Q, KS, Z);

    // KV[b] = K[b]^T V[b]   (TN, K-reduction over SEQ)
    const dim3 gKV(DIM / 128, DIM / 128, BATCH);
    gemm128<1,0,EPI_NONE><<<gKV, thr>>>(K, V, KV, DIM, DIM, DIM, SEQ, nullptr, nullptr,
                                        (size_t)SEQ*DIM, (size_t)SEQ*DIM, (size_t)DIM*DIM, 0);

    // ctx[b] = (Q[b] KV[b]) / Z[b]   (NN)  — ctx overwrites V (dead)
    const dim3 gCtx(DIM / 128, SEQ / 128, BATCH);
    gemm128<0,0,EPI_DIVZ><<<gCtx, thr>>>(Q, KV, CTX, DIM, DIM, DIM, DIM, nullptr, Z,
                                         (size_t)SEQ*DIM, (size_t)DIM*DIM, (size_t)SEQ*DIM, (size_t)SEQ);

    // out = ctx Wo^T + bo
    gemm128<0,1,EPI_BIAS><<<gProj, thr>>>(CTX, Wo, (float*)d_out, DIM, DIM, DIM, DIM, bo, nullptr, 0,0,0,0);
}

// round 4
// speedup vs baseline: 2.1598x; 2.1598x over previous
#include <cuda_runtime.h>
#include <cuda_bf16.h>
#include <cstdint>
#include <math.h>

#define BATCH 8
#define SEQ   4096
#define DIM   1024
#define NROWS (BATCH*SEQ)

// ============================ helpers ============================
__device__ __forceinline__ uint32_t smem_u32(const void* p) {
    uint32_t a;
    asm("{ .reg .u64 t; cvta.to.shared.u64 t, %1; cvt.u32.u64 %0, t; }" : "=r"(a) : "l"(p));
    return a;
}
__device__ __forceinline__ void cp16(uint32_t dst, const void* src) {
    asm volatile("cp.async.cg.shared.global [%0], [%1], 16;" :: "r"(dst), "l"(src) : "memory");
}
__device__ __forceinline__ void cp_commit() {
    asm volatile("cp.async.commit_group;" ::: "memory");
}
__device__ __forceinline__ void ldm4(uint32_t* r, uint32_t addr) {
    asm volatile("ldmatrix.sync.aligned.m8n8.x4.shared.b16 {%0,%1,%2,%3}, [%4];"
                 : "=r"(r[0]), "=r"(r[1]), "=r"(r[2]), "=r"(r[3]) : "r"(addr));
}
__device__ __forceinline__ void mma_bf16(float* c, const uint32_t* a, uint32_t b0, uint32_t b1) {
    asm volatile("mma.sync.aligned.m16n8k16.row.col.f32.bf16.bf16.f32 "
                 "{%0,%1,%2,%3}, {%4,%5,%6,%7}, {%8,%9}, {%0,%1,%2,%3};"
                 : "+f"(c[0]), "+f"(c[1]), "+f"(c[2]), "+f"(c[3])
                 : "r"(a[0]), "r"(a[1]), "r"(a[2]), "r"(a[3]), "r"(b0), "r"(b1));
}

// ============================ scratch ============================
__device__ __nv_bfloat16 g_xh [(size_t)NROWS*DIM];
__device__ __nv_bfloat16 g_xl [(size_t)NROWS*DIM];
__device__ __nv_bfloat16 g_Qh [(size_t)NROWS*DIM];
__device__ __nv_bfloat16 g_Ql [(size_t)NROWS*DIM];
__device__ __nv_bfloat16 g_Kth[(size_t)NROWS*DIM];   // [b][d][n]
__device__ __nv_bfloat16 g_Ktl[(size_t)NROWS*DIM];
__device__ __nv_bfloat16 g_Vth[(size_t)NROWS*DIM];   // [b][e][n]; reused as ctx hi
__device__ __nv_bfloat16 g_Vtl[(size_t)NROWS*DIM];   // reused as ctx lo
__device__ __nv_bfloat16 g_KVh[(size_t)BATCH*DIM*DIM]; // [b][e][d]
__device__ __nv_bfloat16 g_KVl[(size_t)BATCH*DIM*DIM];
__device__ __nv_bfloat16 g_Wqh[DIM*DIM], g_Wql[DIM*DIM];
__device__ __nv_bfloat16 g_Wkh[DIM*DIM], g_Wkl[DIM*DIM];
__device__ __nv_bfloat16 g_Wvh[DIM*DIM], g_Wvl[DIM*DIM];
__device__ __nv_bfloat16 g_Woh[DIM*DIM], g_Wol[DIM*DIM];
__device__ float g_Ksum[BATCH*DIM];
__device__ float g_Z[NROWS];

// ============================ small kernels ============================
__global__ void split_kernel(const float4* __restrict__ src,
                             __nv_bfloat162* __restrict__ hi,
                             __nv_bfloat162* __restrict__ lo, int n4)
{
    for (int i = blockIdx.x * blockDim.x + threadIdx.x; i < n4; i += gridDim.x * blockDim.x) {
        float4 v = src[i];
        __nv_bfloat16 h0 = __float2bfloat16(v.x), h1 = __float2bfloat16(v.y);
        __nv_bfloat16 h2 = __float2bfloat16(v.z), h3 = __float2bfloat16(v.w);
        __nv_bfloat16 l0 = __float2bfloat16(v.x - __bfloat162float(h0));
        __nv_bfloat16 l1 = __float2bfloat16(v.y - __bfloat162float(h1));
        __nv_bfloat16 l2 = __float2bfloat16(v.z - __bfloat162float(h2));
        __nv_bfloat16 l3 = __float2bfloat16(v.w - __bfloat162float(h3));
        hi[2*i]   = __nv_bfloat162{h0, h1};
        hi[2*i+1] = __nv_bfloat162{h2, h3};
        lo[2*i]   = __nv_bfloat162{l0, l1};
        lo[2*i+1] = __nv_bfloat162{l2, l3};
    }
}

__global__ void ksum_kernel(const __nv_bfloat162* __restrict__ Kh,
                            const __nv_bfloat162* __restrict__ Kl,
                            float* __restrict__ Ks)
{
    const int warp = threadIdx.x >> 5, lane = threadIdx.x & 31;
    const int r = blockIdx.x * 8 + warp;
    const size_t base = (size_t)r * (SEQ / 2);
    float s = 0.0f;
    for (int i = lane; i < SEQ / 2; i += 32) {
        float2 h = __bfloat1622float2(Kh[base + i]);
        float2 l = __bfloat1622float2(Kl[base + i]);
        s += h.x + l.x + h.y + l.y;
    }
    #pragma unroll
    for (int o = 16; o; o >>= 1) s += __shfl_xor_sync(0xFFFFFFFFu, s, o);
    if (lane == 0) Ks[r] = s + 1e-6f;
}

__global__ void z_kernel(const __nv_bfloat162* __restrict__ Qh,
                         const __nv_bfloat162* __restrict__ Ql,
                         const float* __restrict__ Ks, float* __restrict__ Z)
{
    const int warp = threadIdx.x >> 5, lane = threadIdx.x & 31;
    const int row = blockIdx.x * 8 + warp;
    const size_t qb = (size_t)row * (DIM / 2);
    const float2* ks = (const float2*)(Ks + (row >> 12) * DIM);
    float s = 0.0f;
    for (int i = lane; i < DIM / 2; i += 32) {
        float2 h = __bfloat1622float2(Qh[qb + i]);
        float2 l = __bfloat1622float2(Ql[qb + i]);
        float2 k = ks[i];
        s += (h.x + l.x) * k.x + (h.y + l.y) * k.y;
    }
    #pragma unroll
    for (int o = 16; o; o >>= 1) s += __shfl_xor_sync(0xFFFFFFFFu, s, o);
    if (lane == 0) Z[row] = s;
}

// ============================ warp-MMA GEMM ============================
// C[m,n] = sum_k A(m,k)*B(n,k), bf16 hi/lo 3-pass, fp32 accum.
// 128x128 tile, BK=64, 8 warps (2x4 -> 64x32 warp tiles), cp.async double buffer.
enum { EP_Q = 0, EP_KT = 1, EP_VT = 2, EP_KV = 3, EP_CTX = 4, EP_OUT = 5 };

#define TILE_BYTES  16384
#define SMEM_BYTES  (8 * TILE_BYTES)
#define TOFF(buf, i) ((((buf) * 4 + (i)) << 14))

template<int EPI>
__global__ __launch_bounds__(256, 1)
void mm_bf16(const __nv_bfloat16* __restrict__ Ah, const __nv_bfloat16* __restrict__ Al,
             const __nv_bfloat16* __restrict__ Bh, const __nv_bfloat16* __restrict__ Bl,
             int K, size_t sA, size_t sB,
             const float* __restrict__ bias, const float* __restrict__ Zv,
             void* __restrict__ Oh, void* __restrict__ Ol)
{
    extern __shared__ char smem[];
    const uint32_t sb = smem_u32(smem);
    const int tid = threadIdx.x, wid = tid >> 5, lane = tid & 31;
    const int wm = wid >> 2, wn = wid & 3;
    const int m0 = blockIdx.y * 128, n0 = blockIdx.x * 128, bz = blockIdx.z;

    const __nv_bfloat16* pAh = Ah + (size_t)bz * sA + (size_t)m0 * K;
    const __nv_bfloat16* pAl = Al + (size_t)bz * sA + (size_t)m0 * K;
    const __nv_bfloat16* pBh = Bh + (size_t)bz * sB + (size_t)n0 * K;
    const __nv_bfloat16* pBl = Bl + (size_t)bz * sB + (size_t)n0 * K;

    // cp.async per-thread coords: row lr (0..127), half lh (0/1), 4x16B
    const int lr = tid >> 1, lh = tid & 1;
    const uint32_t lmask = (uint32_t)((lr & 7) << 4);

    auto issue_chunk = [&](int t) {
        const int buf = t & 1;
        const size_t koff = (size_t)t * 64;
        const __nv_bfloat16* gs[4] = { pAh + koff, pAl + koff, pBh + koff, pBl + koff };
        #pragma unroll
        for (int i = 0; i < 4; i++) {
            const char* src = (const char*)(gs[i] + (size_t)lr * K) + lh * 64;
            const uint32_t dbase = sb + TOFF(buf, i) + lr * 128;
            #pragma unroll
            for (int j = 0; j < 4; j++)
                cp16(dbase + (((uint32_t)(lh * 64 + j * 16)) ^ lmask), src + j * 16);
        }
        cp_commit();
    };

    float acc[4][4][4];
    #pragma unroll
    for (int a = 0; a < 4; a++)
        #pragma unroll
        for (int b = 0; b < 4; b++)
            #pragma unroll
            for (int c = 0; c < 4; c++) acc[a][b][c] = 0.0f;

    // fragment addressing constants
    const int la = lane & 15;
    const uint32_t lb4 = (uint32_t)((lane >> 4) << 4);   // 0 or 16 bytes
    const int rowA = wm * 64 + la;
    const uint32_t maskA = (uint32_t)((rowA & 7) << 4);
    const uint32_t aoff  = (uint32_t)(rowA * 128);
    const int rowB = wn * 32 + la;
    const uint32_t maskB = (uint32_t)((rowB & 7) << 4);
    const uint32_t boff  = (uint32_t)(rowB * 128);

    const int nT = K >> 6;
    issue_chunk(0);
    if (nT > 1) issue_chunk(1);

    for (int t = 0; t < nT; t++) {
        if (t + 1 < nT) asm volatile("cp.async.wait_group 1;" ::: "memory");
        else            asm volatile("cp.async.wait_group 0;" ::: "memory");
        __syncthreads();

        const int buf = t & 1;
        const uint32_t bAh = sb + TOFF(buf, 0) + aoff;
        const uint32_t bAl = sb + TOFF(buf, 1) + aoff;
        const uint32_t bBh = sb + TOFF(buf, 2) + boff;
        const uint32_t bBl = sb + TOFF(buf, 3) + boff;

        #pragma unroll
        for (int s = 0; s < 4; s++) {
            const uint32_t cb = (uint32_t)(s * 32) + lb4;
            const uint32_t cA = cb ^ maskA, cB = cb ^ maskB;
            uint32_t ah[4][4], al[4][4], bh[2][4], bl[2][4];
            #pragma unroll
            for (int mi = 0; mi < 4; mi++) {
                ldm4(ah[mi], bAh + mi * 2048 + cA);
                ldm4(al[mi], bAl + mi * 2048 + cA);
            }
            #pragma unroll
            for (int j2 = 0; j2 < 2; j2++) {
                ldm4(bh[j2], bBh + j2 * 2048 + cB);
                ldm4(bl[j2], bBl + j2 * 2048 + cB);
            }
            #pragma unroll
            for (int mi = 0; mi < 4; mi++)
                #pragma unroll
                for (int nj = 0; nj < 4; nj++) {
                    const int j2 = nj >> 1, p = nj & 1;
                    mma_bf16(acc[mi][nj], ah[mi], bh[j2][p], bh[j2][2 + p]);
                    mma_bf16(acc[mi][nj], ah[mi], bl[j2][p], bl[j2][2 + p]);
                    mma_bf16(acc[mi][nj], al[mi], bh[j2][p], bh[j2][2 + p]);
                }
        }
        __syncthreads();
        if (t + 2 < nT) issue_chunk(t + 2);
    }

    // ---- epilogue ----
    // tile (mi,nj): rows m0+wm*64+mi*16+(lane>>2)+{0,8}, cols n0+wn*32+nj*8+(lane&3)*2+{0,1}
    const int rbase = m0 + wm * 64 + (lane >> 2);
    const int cbase = n0 + wn * 32 + (lane & 3) * 2;
    #pragma unroll
    for (int mi = 0; mi < 4; mi++) {
        #pragma unroll
        for (int gr = 0; gr < 2; gr++) {
            const int m = rbase + mi * 16 + gr * 8;
            float zin = 1.0f;
            if (EPI == EP_CTX) zin = 1.0f / Zv[(size_t)bz * SEQ + m];
            #pragma unroll
            for (int nj = 0; nj < 4; nj++) {
                const int col = cbase + nj * 8;
                float v0 = acc[mi][nj][gr * 2];
                float v1 = acc[mi][nj][gr * 2 + 1];
                if (EPI == EP_Q || EPI == EP_KT || EPI == EP_VT || EPI == EP_OUT) {
                    v0 += bias[col]; v1 += bias[col + 1];
                }
                if (EPI == EP_Q || EPI == EP_KT) {
                    v0 = v0 > 0.0f ? v0 + 1.0f : expf(v0);
                    v1 = v1 > 0.0f ? v1 + 1.0f : expf(v1);
                }
                if (EPI == EP_CTX) { v0 *= zin; v1 *= zin; }

                if (EPI == EP_OUT) {
                    float* o = (float*)Oh;
                    *(float2*)(o + (size_t)m * DIM + col) = make_float2(v0, v1);
                } else {
                    __nv_bfloat16 h0 = __float2bfloat16(v0), h1 = __float2bfloat16(v1);
                    __nv_bfloat16 l0 = __float2bfloat16(v0 - __bfloat162float(h0));
                    __nv_bfloat16 l1 = __float2bfloat16(v1 - __bfloat162float(h1));
                    __nv_bfloat16* oh = (__nv_bfloat16*)Oh;
                    __nv_bfloat16* ol = (__nv_bfloat16*)Ol;
                    if (EPI == EP_Q) {
                        const size_t a = (size_t)m * DIM + col;
                        *(__nv_bfloat162*)(oh + a) = __nv_bfloat162{h0, h1};
                        *(__nv_bfloat162*)(ol + a) = __nv_bfloat162{l0, l1};
                    } else if (EPI == EP_CTX) {
                        const size_t a = ((size_t)bz * SEQ + m) * DIM + col;
                        *(__nv_bfloat162*)(oh + a) = __nv_bfloat162{h0, h1};
                        *(__nv_bfloat162*)(ol + a) = __nv_bfloat162{l0, l1};
                    } else if (EPI == EP_KT || EPI == EP_VT) {
                        // m = global row over (b, seq); transposed store [b][chan][seq]
                        const int b = m >> 12, nl = m & 4095;
                        const size_t a0 = (size_t)b * DIM * SEQ + (size_t)col * SEQ + nl;
                        oh[a0] = h0; ol[a0] = l0;
                        oh[a0 + SEQ] = h1; ol[a0 + SEQ] = l1;
                    } else { // EP_KV: out[b][n][m] (d = m contiguous)
                        const size_t a0 = (size_t)bz * DIM * DIM + (size_t)col * DIM + m;
                        oh[a0] = h0; ol[a0] = l0;
                        oh[a0 + DIM] = h1; ol[a0 + DIM] = l1;
                    }
                }
            }
        }
    }
}

// ============================ launch ============================
extern "C" void kernel_launch(void* const* d_in, const int* in_sizes, int n_in,
                              void* d_out, int out_size)
{
    const float* x  = (const float*)d_in[0];
    const float* Wq = (const float*)d_in[1];
    const float* bq = (const float*)d_in[2];
    const float* Wk = (const float*)d_in[3];
    const float* bk = (const float*)d_in[4];
    const float* Wv = (const float*)d_in[5];
    const float* bv = (const float*)d_in[6];
    const float* Wo = (const float*)d_in[7];
    const float* bo = (const float*)d_in[8];

    cudaFuncSetAttribute(mm_bf16<EP_Q>,   cudaFuncAttributeMaxDynamicSharedMemorySize, SMEM_BYTES);
    cudaFuncSetAttribute(mm_bf16<EP_KT>,  cudaFuncAttributeMaxDynamicSharedMemorySize, SMEM_BYTES);
    cudaFuncSetAttribute(mm_bf16<EP_VT>,  cudaFuncAttributeMaxDynamicSharedMemorySize, SMEM_BYTES);
    cudaFuncSetAttribute(mm_bf16<EP_KV>,  cudaFuncAttributeMaxDynamicSharedMemorySize, SMEM_BYTES);
    cudaFuncSetAttribute(mm_bf16<EP_CTX>, cudaFuncAttributeMaxDynamicSharedMemorySize, SMEM_BYTES);
    cudaFuncSetAttribute(mm_bf16<EP_OUT>, cudaFuncAttributeMaxDynamicSharedMemorySize, SMEM_BYTES);

    __nv_bfloat16 *xh, *xl, *Qh, *Ql, *Kth, *Ktl, *Vth, *Vtl, *KVh, *KVl;
    __nv_bfloat16 *Wqh, *Wql, *Wkh, *Wkl, *Wvh, *Wvl, *Woh, *Wol;
    float *Ks, *Z;
    cudaGetSymbolAddress((void**)&xh,  g_xh);  cudaGetSymbolAddress((void**)&xl,  g_xl);
    cudaGetSymbolAddress((void**)&Qh,  g_Qh);  cudaGetSymbolAddress((void**)&Ql,  g_Ql);
    cudaGetSymbolAddress((void**)&Kth, g_Kth); cudaGetSymbolAddress((void**)&Ktl, g_Ktl);
    cudaGetSymbolAddress((void**)&Vth, g_Vth); cudaGetSymbolAddress((void**)&Vtl, g_Vtl);
    cudaGetSymbolAddress((void**)&KVh, g_KVh); cudaGetSymbolAddress((void**)&KVl, g_KVl);
    cudaGetSymbolAddress((void**)&Wqh, g_Wqh); cudaGetSymbolAddress((void**)&Wql, g_Wql);
    cudaGetSymbolAddress((void**)&Wkh, g_Wkh); cudaGetSymbolAddress((void**)&Wkl, g_Wkl);
    cudaGetSymbolAddress((void**)&Wvh, g_Wvh); cudaGetSymbolAddress((void**)&Wvl, g_Wvl);
    cudaGetSymbolAddress((void**)&Woh, g_Woh); cudaGetSymbolAddress((void**)&Wol, g_Wol);
    cudaGetSymbolAddress((void**)&Ks,  g_Ksum); cudaGetSymbolAddress((void**)&Z, g_Z);

    split_kernel<<<2048, 256>>>((const float4*)x,  (__nv_bfloat162*)xh,  (__nv_bfloat162*)xl,  NROWS*DIM/4);
    split_kernel<<<512,  256>>>((const float4*)Wq, (__nv_bfloat162*)Wqh, (__nv_bfloat162*)Wql, DIM*DIM/4);
    split_kernel<<<512,  256>>>((const float4*)Wk, (__nv_bfloat162*)Wkh, (__nv_bfloat162*)Wkl, DIM*DIM/4);
    split_kernel<<<512,  256>>>((const float4*)Wv, (__nv_bfloat162*)Wvh, (__nv_bfloat162*)Wvl, DIM*DIM/4);
    split_kernel<<<512,  256>>>((const float4*)Wo, (__nv_bfloat162*)Woh, (__nv_bfloat162*)Wol, DIM*DIM/4);

    const dim3 thr(256);
    const dim3 gProj(DIM/128, NROWS/128, 1);

    mm_bf16<EP_Q> <<<gProj, thr, SMEM_BYTES>>>(xh, xl, Wqh, Wql, DIM, 0, 0, bq, nullptr, Qh, Ql);
    mm_bf16<EP_KT><<<gProj, thr, SMEM_BYTES>>>(xh, xl, Wkh, Wkl, DIM, 0, 0, bk, nullptr, Kth, Ktl);
    mm_bf16<EP_VT><<<gProj, thr, SMEM_BYTES>>>(xh, xl, Wvh, Wvl, DIM, 0, 0, bv, nullptr, Vth, Vtl);

    ksum_kernel<<<BATCH*DIM/8, 256>>>((const __nv_bfloat162*)Kth, (const __nv_bfloat162*)Ktl, Ks);
    z_kernel<<<NROWS/8, 256>>>((const __nv_bfloat162*)Qh, (const __nv_bfloat162*)Ql, Ks, Z);

    // KVt[b][e][d] = sum_n Kt[b][d][n] * Vt[b][e][n]
    const dim3 gKV(DIM/128, DIM/128, BATCH);
    mm_bf16<EP_KV><<<gKV, thr, SMEM_BYTES>>>(Kth, Ktl, Vth, Vtl, SEQ,
                                             (size_t)DIM*SEQ, (size_t)DIM*SEQ,
                                             nullptr, nullptr, KVh, KVl);

    // ctx[b][n][e] = (Q[b][n][:] . KVt[b][e][:]) / Z  — overwrites Vt (dead)
    __nv_bfloat16 *Ch = Vth, *Cl = Vtl;
    const dim3 gCtx(DIM/128, SEQ/128, BATCH);
    mm_bf16<EP_CTX><<<gCtx, thr, SMEM_BYTES>>>(Qh, Ql, KVh, KVl, DIM,
                                               (size_t)SEQ*DIM, (size_t)DIM*DIM,
                                               nullptr, Z, Ch, Cl);

    mm_bf16<EP_OUT><<<gProj, thr, SMEM_BYTES>>>(Ch, Cl, Woh, Wol, DIM, 0, 0, bo, nullptr, d_out, nullptr);
}

// round 5
// speedup vs baseline: 3.1034x; 1.4369x over previous
#include <cuda_runtime.h>
#include <cuda_fp16.h>
#include <cstdint>
#include <math.h>

#define BATCH 8
#define SEQ   4096
#define DIM   1024
#define NROWS (BATCH*SEQ)

// ============================ helpers ============================
__device__ __forceinline__ uint32_t smem_u32(const void* p) {
    uint32_t a;
    asm("{ .reg .u64 t; cvta.to.shared.u64 t, %1; cvt.u32.u64 %0, t; }" : "=r"(a) : "l"(p));
    return a;
}
__device__ __forceinline__ void cp16(uint32_t dst, const void* src) {
    asm volatile("cp.async.cg.shared.global [%0], [%1], 16;" :: "r"(dst), "l"(src) : "memory");
}
__device__ __forceinline__ void cp_commit() {
    asm volatile("cp.async.commit_group;" ::: "memory");
}
__device__ __forceinline__ void ldm4(uint32_t* r, uint32_t addr) {
    asm volatile("ldmatrix.sync.aligned.m8n8.x4.shared.b16 {%0,%1,%2,%3}, [%4];"
                 : "=r"(r[0]), "=r"(r[1]), "=r"(r[2]), "=r"(r[3]) : "r"(addr));
}
__device__ __forceinline__ void mma_f16(float* c, const uint32_t* a, uint32_t b0, uint32_t b1) {
    asm volatile("mma.sync.aligned.m16n8k16.row.col.f32.f16.f16.f32 "
                 "{%0,%1,%2,%3}, {%4,%5,%6,%7}, {%8,%9}, {%0,%1,%2,%3};"
                 : "+f"(c[0]), "+f"(c[1]), "+f"(c[2]), "+f"(c[3])
                 : "r"(a[0]), "r"(a[1]), "r"(a[2]), "r"(a[3]), "r"(b0), "r"(b1));
}

// ============================ scratch ============================
__device__ __half g_xh [(size_t)NROWS*DIM];
__device__ __half g_Qh [(size_t)NROWS*DIM];
__device__ __half g_Kth[(size_t)NROWS*DIM];   // [b][d][n]; reused as ctx [b][n][e]
__device__ __half g_Vth[(size_t)NROWS*DIM];   // [b][e][n]
__device__ __half g_Vtl[(size_t)NROWS*DIM];
__device__ __half g_KVth[(size_t)BATCH*DIM*DIM]; // [b][e][d]
__device__ __half g_KVtl[(size_t)BATCH*DIM*DIM];
__device__ __half g_Wqh[DIM*DIM], g_Wql[DIM*DIM];
__device__ __half g_Wkh[DIM*DIM], g_Wkl[DIM*DIM];
__device__ __half g_Wvh[DIM*DIM], g_Wvl[DIM*DIM];
__device__ __half g_Woh[DIM*DIM], g_Wol[DIM*DIM];
__device__ float g_Ksum[BATCH*DIM];
__device__ float g_Z[NROWS];

// ============================ small kernels ============================
__global__ void split2_kernel(const float4* __restrict__ src,
                              __half2* __restrict__ hi, __half2* __restrict__ lo, int n4)
{
    for (int i = blockIdx.x * blockDim.x + threadIdx.x; i < n4; i += gridDim.x * blockDim.x) {
        float4 v = src[i];
        __half h0 = __float2half_rn(v.x), h1 = __float2half_rn(v.y);
        __half h2 = __float2half_rn(v.z), h3 = __float2half_rn(v.w);
        __half l0 = __float2half_rn(v.x - __half2float(h0));
        __half l1 = __float2half_rn(v.y - __half2float(h1));
        __half l2 = __float2half_rn(v.z - __half2float(h2));
        __half l3 = __float2half_rn(v.w - __half2float(h3));
        hi[2*i]   = __half2{h0, h1}; hi[2*i+1] = __half2{h2, h3};
        lo[2*i]   = __half2{l0, l1}; lo[2*i+1] = __half2{l2, l3};
    }
}
__global__ void split1_kernel(const float4* __restrict__ src, __half2* __restrict__ hi, int n4)
{
    for (int i = blockIdx.x * blockDim.x + threadIdx.x; i < n4; i += gridDim.x * blockDim.x) {
        float4 v = src[i];
        hi[2*i]   = __half2{__float2half_rn(v.x), __float2half_rn(v.y)};
        hi[2*i+1] = __half2{__float2half_rn(v.z), __float2half_rn(v.w)};
    }
}

// Ksum[r] = sum_n Kt[r][n] + 1e-6   (r = b*DIM + d; Kt rows are seq-contiguous)
__global__ void ksum_kernel(const __half2* __restrict__ Kh, float* __restrict__ Ks)
{
    const int warp = threadIdx.x >> 5, lane = threadIdx.x & 31;
    const int r = blockIdx.x * 8 + warp;
    const size_t base = (size_t)r * (SEQ / 2);
    float s = 0.0f;
    for (int i = lane; i < SEQ / 2; i += 32) {
        float2 h = __half22float2(Kh[base + i]);
        s += h.x + h.y;
    }
    #pragma unroll
    for (int o = 16; o; o >>= 1) s += __shfl_xor_sync(0xFFFFFFFFu, s, o);
    if (lane == 0) Ks[r] = s + 1e-6f;
}

__global__ void z_kernel(const __half2* __restrict__ Qh,
                         const float* __restrict__ Ks, float* __restrict__ Z)
{
    const int warp = threadIdx.x >> 5, lane = threadIdx.x & 31;
    const int row = blockIdx.x * 8 + warp;
    const size_t qb = (size_t)row * (DIM / 2);
    const float2* ks = (const float2*)(Ks + (row >> 12) * DIM);
    float s = 0.0f;
    for (int i = lane; i < DIM / 2; i += 32) {
        float2 h = __half22float2(Qh[qb + i]);
        float2 k = ks[i];
        s += h.x * k.x + h.y * k.y;
    }
    #pragma unroll
    for (int o = 16; o; o >>= 1) s += __shfl_xor_sync(0xFFFFFFFFu, s, o);
    if (lane == 0) Z[row] = s;
}

// ============================ warp-MMA GEMM ============================
// C[m,n] = sum_k A(m,k)*B(n,k); A fp16 hi-only, B fp16 hi+lo (2-pass), fp32 accum.
// 128x128 tile, BK=64, 8 warps (64x32 warp tiles), 4-stage cp.async pipeline.
enum { EP_Q = 0, EP_KT = 1, EP_VT = 2, EP_KV = 3, EP_CTX = 4, EP_OUT = 5 };

#define TILE_BYTES  16384
#define SMEM_BYTES  (12 * TILE_BYTES)          // 4 stages x 3 tiles
#define TOFF(buf, i) ((((buf) * 3 + (i)) << 14))

template<int EPI>
__global__ __launch_bounds__(256, 1)
void mm_f16(const __half* __restrict__ Ah,
            const __half* __restrict__ Bh, const __half* __restrict__ Bl,
            int K, size_t sA, size_t sB,
            const float* __restrict__ bias, const float* __restrict__ Zv,
            void* __restrict__ Oh, void* __restrict__ Ol)
{
    extern __shared__ char smem[];
    const uint32_t sb = smem_u32(smem);
    const int tid = threadIdx.x, wid = tid >> 5, lane = tid & 31;
    const int wm = wid >> 2, wn = wid & 3;
    const int m0 = blockIdx.y * 128, n0 = blockIdx.x * 128, bz = blockIdx.z;

    const __half* pAh = Ah + (size_t)bz * sA + (size_t)m0 * K;
    const __half* pBh = Bh + (size_t)bz * sB + (size_t)n0 * K;
    const __half* pBl = Bl + (size_t)bz * sB + (size_t)n0 * K;

    const int lr = tid >> 1, lh = tid & 1;
    const uint32_t lmask = (uint32_t)((lr & 7) << 4);

    auto issue_chunk = [&](int t) {
        const int buf = t & 3;
        const size_t koff = (size_t)t * 64;
        const __half* gs[3] = { pAh + koff, pBh + koff, pBl + koff };
        #pragma unroll
        for (int i = 0; i < 3; i++) {
            const char* src = (const char*)(gs[i] + (size_t)lr * K) + lh * 64;
            const uint32_t dbase = sb + TOFF(buf, i) + lr * 128;
            #pragma unroll
            for (int j = 0; j < 4; j++)
                cp16(dbase + (((uint32_t)(lh * 64 + j * 16)) ^ lmask), src + j * 16);
        }
        cp_commit();
    };

    float acc[4][4][4];
    #pragma unroll
    for (int a = 0; a < 4; a++)
        #pragma unroll
        for (int b = 0; b < 4; b++)
            #pragma unroll
            for (int c = 0; c < 4; c++) acc[a][b][c] = 0.0f;

    const int la = lane & 15;
    const uint32_t lb4 = (uint32_t)((lane >> 4) << 4);
    const int rowA = wm * 64 + la;
    const uint32_t maskA = (uint32_t)((rowA & 7) << 4);
    const uint32_t aoff  = (uint32_t)(rowA * 128);
    const int rowB = wn * 32 + la;
    const uint32_t maskB = (uint32_t)((rowB & 7) << 4);
    const uint32_t boff  = (uint32_t)(rowB * 128);

    const int nT = K >> 6;
    issue_chunk(0); issue_chunk(1); issue_chunk(2);

    for (int t = 0; t < nT; t++) {
        const int rem = nT - 1 - t;
        if (rem >= 2)      asm volatile("cp.async.wait_group 2;" ::: "memory");
        else if (rem == 1) asm volatile("cp.async.wait_group 1;" ::: "memory");
        else               asm volatile("cp.async.wait_group 0;" ::: "memory");
        __syncthreads();
        if (t + 3 < nT) issue_chunk(t + 3);

        const int buf = t & 3;
        const uint32_t bAh = sb + TOFF(buf, 0) + aoff;
        const uint32_t bBh = sb + TOFF(buf, 1) + boff;
        const uint32_t bBl = sb + TOFF(buf, 2) + boff;

        #pragma unroll
        for (int s = 0; s < 4; s++) {
            const uint32_t cb = (uint32_t)(s * 32) + lb4;
            const uint32_t cA = cb ^ maskA, cB = cb ^ maskB;
            uint32_t ah[4][4], bh[2][4], bl[2][4];
            #pragma unroll
            for (int mi = 0; mi < 4; mi++) ldm4(ah[mi], bAh + mi * 2048 + cA);
            #pragma unroll
            for (int j2 = 0; j2 < 2; j2++) {
                ldm4(bh[j2], bBh + j2 * 2048 + cB);
                ldm4(bl[j2], bBl + j2 * 2048 + cB);
            }
            #pragma unroll
            for (int mi = 0; mi < 4; mi++)
                #pragma unroll
                for (int nj = 0; nj < 4; nj++) {
                    const int j2 = nj >> 1, p = nj & 1;
                    mma_f16(acc[mi][nj], ah[mi], bh[j2][p], bh[j2][2 + p]);
                    mma_f16(acc[mi][nj], ah[mi], bl[j2][p], bl[j2][2 + p]);
                }
        }
    }

    // ---- epilogue ----
    const int rbase = m0 + wm * 64 + (lane >> 2);
    const int cbase = n0 + wn * 32 + (lane & 3) * 2;
    #pragma unroll
    for (int mi = 0; mi < 4; mi++) {
        #pragma unroll
        for (int gr = 0; gr < 2; gr++) {
            const int m = rbase + mi * 16 + gr * 8;
            float zin = 1.0f;
            if (EPI == EP_CTX) zin = 1.0f / Zv[(size_t)bz * SEQ + m];
            #pragma unroll
            for (int nj = 0; nj < 4; nj++) {
                const int col = cbase + nj * 8;
                float v0 = acc[mi][nj][gr * 2];
                float v1 = acc[mi][nj][gr * 2 + 1];
                if (EPI == EP_Q || EPI == EP_KT || EPI == EP_VT || EPI == EP_OUT) {
                    v0 += bias[col]; v1 += bias[col + 1];
                }
                if (EPI == EP_Q || EPI == EP_KT) {
                    v0 = v0 > 0.0f ? v0 + 1.0f : expf(v0);
                    v1 = v1 > 0.0f ? v1 + 1.0f : expf(v1);
                }
                if (EPI == EP_CTX) { v0 *= zin; v1 *= zin; }

                if (EPI == EP_OUT) {
                    float* o = (float*)Oh;
                    *(float2*)(o + (size_t)m * DIM + col) = make_float2(v0, v1);
                } else {
                    __half h0 = __float2half_rn(v0), h1 = __float2half_rn(v1);
                    __half* oh = (__half*)Oh;
                    __half* ol = (__half*)Ol;
                    if (EPI == EP_Q) {
                        *(__half2*)(oh + (size_t)m * DIM + col) = __half2{h0, h1};
                    } else if (EPI == EP_CTX) {
                        *(__half2*)(oh + ((size_t)bz * SEQ + m) * DIM + col) = __half2{h0, h1};
                    } else if (EPI == EP_KT) {
                        const int b = m >> 12, nl = m & 4095;
                        const size_t a0 = (size_t)b * DIM * SEQ + (size_t)col * SEQ + nl;
                        oh[a0] = h0; oh[a0 + SEQ] = h1;
                    } else if (EPI == EP_VT) {
                        const int b = m >> 12, nl = m & 4095;
                        const size_t a0 = (size_t)b * DIM * SEQ + (size_t)col * SEQ + nl;
                        __half l0 = __float2half_rn(v0 - __half2float(h0));
                        __half l1 = __float2half_rn(v1 - __half2float(h1));
                        oh[a0] = h0; ol[a0] = l0;
                        oh[a0 + SEQ] = h1; ol[a0 + SEQ] = l1;
                    } else { // EP_KV: store KV^T[b][e][d], m = d contiguous
                        const size_t a0 = (size_t)bz * DIM * DIM + (size_t)col * DIM + m;
                        __half l0 = __float2half_rn(v0 - __half2float(h0));
                        __half l1 = __float2half_rn(v1 - __half2float(h1));
                        oh[a0] = h0; ol[a0] = l0;
                        oh[a0 + DIM] = h1; ol[a0 + DIM] = l1;
                    }
                }
            }
        }
    }
}

// ============================ launch ============================
extern "C" void kernel_launch(void* const* d_in, const int* in_sizes, int n_in,
                              void* d_out, int out_size)
{
    const float* x  = (const float*)d_in[0];
    const float* Wq = (const float*)d_in[1];
    const float* bq = (const float*)d_in[2];
    const float* Wk = (const float*)d_in[3];
    const float* bk = (const float*)d_in[4];
    const float* Wv = (const float*)d_in[5];
    const float* bv = (const float*)d_in[6];
    const float* Wo = (const float*)d_in[7];
    const float* bo = (const float*)d_in[8];

    cudaFuncSetAttribute(mm_f16<EP_Q>,   cudaFuncAttributeMaxDynamicSharedMemorySize, SMEM_BYTES);
    cudaFuncSetAttribute(mm_f16<EP_KT>,  cudaFuncAttributeMaxDynamicSharedMemorySize, SMEM_BYTES);
    cudaFuncSetAttribute(mm_f16<EP_VT>,  cudaFuncAttributeMaxDynamicSharedMemorySize, SMEM_BYTES);
    cudaFuncSetAttribute(mm_f16<EP_KV>,  cudaFuncAttributeMaxDynamicSharedMemorySize, SMEM_BYTES);
    cudaFuncSetAttribute(mm_f16<EP_CTX>, cudaFuncAttributeMaxDynamicSharedMemorySize, SMEM_BYTES);
    cudaFuncSetAttribute(mm_f16<EP_OUT>, cudaFuncAttributeMaxDynamicSharedMemorySize, SMEM_BYTES);

    __half *xh, *Qh, *Kth, *Vth, *Vtl, *KVth, *KVtl;
    __half *Wqh, *Wql, *Wkh, *Wkl, *Wvh, *Wvl, *Woh, *Wol;
    float *Ks, *Z;
    cudaGetSymbolAddress((void**)&xh,   g_xh);
    cudaGetSymbolAddress((void**)&Qh,   g_Qh);
    cudaGetSymbolAddress((void**)&Kth,  g_Kth);
    cudaGetSymbolAddress((void**)&Vth,  g_Vth);  cudaGetSymbolAddress((void**)&Vtl,  g_Vtl);
    cudaGetSymbolAddress((void**)&KVth, g_KVth); cudaGetSymbolAddress((void**)&KVtl, g_KVtl);
    cudaGetSymbolAddress((void**)&Wqh,  g_Wqh);  cudaGetSymbolAddress((void**)&Wql,  g_Wql);
    cudaGetSymbolAddress((void**)&Wkh,  g_Wkh);  cudaGetSymbolAddress((void**)&Wkl,  g_Wkl);
    cudaGetSymbolAddress((void**)&Wvh,  g_Wvh);  cudaGetSymbolAddress((void**)&Wvl,  g_Wvl);
    cudaGetSymbolAddress((void**)&Woh,  g_Woh);  cudaGetSymbolAddress((void**)&Wol,  g_Wol);
    cudaGetSymbolAddress((void**)&Ks,   g_Ksum); cudaGetSymbolAddress((void**)&Z,    g_Z);

    split1_kernel<<<2048, 256>>>((const float4*)x,  (__half2*)xh, NROWS*DIM/4);
    split2_kernel<<<512,  256>>>((const float4*)Wq, (__half2*)Wqh, (__half2*)Wql, DIM*DIM/4);
    split2_kernel<<<512,  256>>>((const float4*)Wk, (__half2*)Wkh, (__half2*)Wkl, DIM*DIM/4);
    split2_kernel<<<512,  256>>>((const float4*)Wv, (__half2*)Wvh, (__half2*)Wvl, DIM*DIM/4);
    split2_kernel<<<512,  256>>>((const float4*)Wo, (__half2*)Woh, (__half2*)Wol, DIM*DIM/4);

    const dim3 thr(256);
    const dim3 gProj(DIM/128, NROWS/128, 1);

    mm_f16<EP_Q> <<<gProj, thr, SMEM_BYTES>>>(xh, Wqh, Wql, DIM, 0, 0, bq, nullptr, Qh, nullptr);
    mm_f16<EP_KT><<<gProj, thr, SMEM_BYTES>>>(xh, Wkh, Wkl, DIM, 0, 0, bk, nullptr, Kth, nullptr);
    mm_f16<EP_VT><<<gProj, thr, SMEM_BYTES>>>(xh, Wvh, Wvl, DIM, 0, 0, bv, nullptr, Vth, Vtl);

    ksum_kernel<<<BATCH*DIM/8, 256>>>((const __half2*)Kth, Ks);
    z_kernel<<<NROWS/8, 256>>>((const __half2*)Qh, Ks, Z);

    // KV^T[b][e][d] = sum_n Kt[b][d][n] * Vt[b][e][n]
    const dim3 gKV(DIM/128, DIM/128, BATCH);
    mm_f16<EP_KV><<<gKV, thr, SMEM_BYTES>>>(Kth, Vth, Vtl, SEQ,
                                            (size_t)DIM*SEQ, (size_t)DIM*SEQ,
                                            nullptr, nullptr, KVth, KVtl);

    // ctx[b][n][e] = (Q[b][n][:] . KVt[b][e][:]) / Z  — overwrites Kt (dead)
    __half* CTX = Kth;
    const dim3 gCtx(DIM/128, SEQ/128, BATCH);
    mm_f16<EP_CTX><<<gCtx, thr, SMEM_BYTES>>>(Qh, KVth, KVtl, DIM,
                                              (size_t)SEQ*DIM, (size_t)DIM*DIM,
                                              nullptr, Z, CTX, nullptr);

    mm_f16<EP_OUT><<<gProj, thr, SMEM_BYTES>>>(CTX, Woh, Wol, DIM, 0, 0, bo, nullptr, d_out, nullptr);
}

// round 6
// speedup vs baseline: 4.9018x; 1.5795x over previous
#include <cuda_runtime.h>
#include <cuda_fp16.h>
#include <cstdint>
#include <math.h>

#define BATCH 8
#define SEQ   4096
#define DIM   1024
#define NROWS (BATCH*SEQ)

// ============================ helpers ============================
__device__ __forceinline__ uint32_t smem_u32(const void* p) {
    uint32_t a;
    asm("{ .reg .u64 t; cvta.to.shared.u64 t, %1; cvt.u32.u64 %0, t; }" : "=r"(a) : "l"(p));
    return a;
}
__device__ __forceinline__ void cp16(uint32_t dst, const void* src) {
    asm volatile("cp.async.cg.shared.global [%0], [%1], 16;" :: "r"(dst), "l"(src) : "memory");
}
__device__ __forceinline__ void cp_commit() {
    asm volatile("cp.async.commit_group;" ::: "memory");
}
__device__ __forceinline__ void ldm4(uint32_t* r, uint32_t addr) {
    asm volatile("ldmatrix.sync.aligned.m8n8.x4.shared.b16 {%0,%1,%2,%3}, [%4];"
                 : "=r"(r[0]), "=r"(r[1]), "=r"(r[2]), "=r"(r[3]) : "r"(addr));
}
__device__ __forceinline__ void mma_f16(float* c, const uint32_t* a, uint32_t b0, uint32_t b1) {
    asm volatile("mma.sync.aligned.m16n8k16.row.col.f32.f16.f16.f32 "
                 "{%0,%1,%2,%3}, {%4,%5,%6,%7}, {%8,%9}, {%0,%1,%2,%3};"
                 : "+f"(c[0]), "+f"(c[1]), "+f"(c[2]), "+f"(c[3])
                 : "r"(a[0]), "r"(a[1]), "r"(a[2]), "r"(a[3]), "r"(b0), "r"(b1));
}

// ============================ scratch ============================
__device__ __half g_xh [(size_t)NROWS*DIM];
__device__ __half g_Qh [(size_t)NROWS*DIM];
__device__ __half g_Kth[(size_t)NROWS*DIM];     // [b][d][n]; reused as ctx [b][n][e]
__device__ __half g_Vth[(size_t)NROWS*DIM];     // [b][e][n]
__device__ __half g_KVth[(size_t)BATCH*DIM*DIM];// [b][e][d]
__device__ __half g_Wqh[DIM*DIM];
__device__ __half g_Wkh[DIM*DIM];
__device__ __half g_Wvh[DIM*DIM];
__device__ __half g_Woh[DIM*DIM];
__device__ float g_Ksum[BATCH*DIM];
__device__ float g_Z[NROWS];

// ============================ small kernels ============================
__global__ void split1_kernel(const float4* __restrict__ src, __half2* __restrict__ hi, int n4)
{
    for (int i = blockIdx.x * blockDim.x + threadIdx.x; i < n4; i += gridDim.x * blockDim.x) {
        float4 v = src[i];
        hi[2*i]   = __half2{__float2half_rn(v.x), __float2half_rn(v.y)};
        hi[2*i+1] = __half2{__float2half_rn(v.z), __float2half_rn(v.w)};
    }
}

// Ksum[r] = sum_n Kt[r][n] + 1e-6   (r = b*DIM + d; Kt rows are seq-contiguous)
__global__ void ksum_kernel(const __half2* __restrict__ Kh, float* __restrict__ Ks)
{
    const int warp = threadIdx.x >> 5, lane = threadIdx.x & 31;
    const int r = blockIdx.x * 8 + warp;
    const size_t base = (size_t)r * (SEQ / 2);
    float s = 0.0f;
    for (int i = lane; i < SEQ / 2; i += 32) {
        float2 h = __half22float2(Kh[base + i]);
        s += h.x + h.y;
    }
    #pragma unroll
    for (int o = 16; o; o >>= 1) s += __shfl_xor_sync(0xFFFFFFFFu, s, o);
    if (lane == 0) Ks[r] = s + 1e-6f;
}

__global__ void z_kernel(const __half2* __restrict__ Qh,
                         const float* __restrict__ Ks, float* __restrict__ Z)
{
    const int warp = threadIdx.x >> 5, lane = threadIdx.x & 31;
    const int row = blockIdx.x * 8 + warp;
    const size_t qb = (size_t)row * (DIM / 2);
    const float2* ks = (const float2*)(Ks + (row >> 12) * DIM);
    float s = 0.0f;
    for (int i = lane; i < DIM / 2; i += 32) {
        float2 h = __half22float2(Qh[qb + i]);
        float2 k = ks[i];
        s += h.x * k.x + h.y * k.y;
    }
    #pragma unroll
    for (int o = 16; o; o >>= 1) s += __shfl_xor_sync(0xFFFFFFFFu, s, o);
    if (lane == 0) Z[row] = s;
}

// ============================ warp-MMA GEMM ============================
// C[m,n] = sum_k A(m,k)*B(n,k); fp16 single-pass, fp32 accum.
// Block tile 128x256, BK=64, 8 warps (2x4 -> 64x64 warp tiles), 4-stage cp.async.
enum { EP_Q = 0, EP_KT = 1, EP_VT = 2, EP_KV = 3, EP_CTX = 4, EP_OUT = 5 };

#define STAGE_BYTES 49152               // A 16KB + B 32KB
#define SMEM_BYTES  (4 * STAGE_BYTES)   // 192 KB
#define AOFFS(buf)  ((buf) * STAGE_BYTES)
#define BOFFS(buf)  ((buf) * STAGE_BYTES + 16384)

template<int EPI>
__global__ __launch_bounds__(256, 1)
void mm_f16(const __half* __restrict__ Ah, const __half* __restrict__ Bh,
            int K, size_t sA, size_t sB,
            const float* __restrict__ bias, const float* __restrict__ Zv,
            void* __restrict__ Oh)
{
    extern __shared__ char smem[];
    const uint32_t sb = smem_u32(smem);
    const int tid = threadIdx.x, wid = tid >> 5, lane = tid & 31;
    const int wm = wid >> 2, wn = wid & 3;     // 2 x 4 warps
    const int m0 = blockIdx.y * 128, n0 = blockIdx.x * 256, bz = blockIdx.z;

    const __half* pA = Ah + (size_t)bz * sA + (size_t)m0 * K;
    const __half* pB = Bh + (size_t)bz * sB + (size_t)n0 * K;

    // cp.async coords: A: 128 rows, 2 threads/row (64B each). B: 256 rows, 1 thread/row (128B).
    const int alr = tid >> 1, alh = tid & 1;
    const uint32_t amask = (uint32_t)((alr & 7) << 4);
    const uint32_t bmask = (uint32_t)((tid & 7) << 4);

    auto issue_chunk = [&](int t) {
        const int buf = t & 3;
        const size_t koff = (size_t)t * 64;
        {   // A tile
            const char* src = (const char*)(pA + koff + (size_t)alr * K) + alh * 64;
            const uint32_t dbase = sb + AOFFS(buf) + alr * 128;
            #pragma unroll
            for (int j = 0; j < 4; j++)
                cp16(dbase + (((uint32_t)(alh * 64 + j * 16)) ^ amask), src + j * 16);
        }
        {   // B tile: one full 128B row per thread
            const char* src = (const char*)(pB + koff + (size_t)tid * K);
            const uint32_t dbase = sb + BOFFS(buf) + tid * 128;
            #pragma unroll
            for (int j = 0; j < 8; j++)
                cp16(dbase + (((uint32_t)(j * 16)) ^ bmask), src + j * 16);
        }
        cp_commit();
    };

    float acc[4][8][4];
    #pragma unroll
    for (int a = 0; a < 4; a++)
        #pragma unroll
        for (int b = 0; b < 8; b++)
            #pragma unroll
            for (int c = 0; c < 4; c++) acc[a][b][c] = 0.0f;

    const int la = lane & 15;
    const uint32_t lb4 = (uint32_t)((lane >> 4) << 4);
    const uint32_t maskA = (uint32_t)((la & 7) << 4);
    const uint32_t aoff  = (uint32_t)((wm * 64 + la) * 128);
    const uint32_t boff  = (uint32_t)((wn * 64 + la) * 128);

    const int nT = K >> 6;
    issue_chunk(0); issue_chunk(1); issue_chunk(2);

    for (int t = 0; t < nT; t++) {
        const int rem = nT - 1 - t;
        if (rem >= 2)      asm volatile("cp.async.wait_group 2;" ::: "memory");
        else if (rem == 1) asm volatile("cp.async.wait_group 1;" ::: "memory");
        else               asm volatile("cp.async.wait_group 0;" ::: "memory");
        __syncthreads();
        if (t + 3 < nT) issue_chunk(t + 3);

        const int buf = t & 3;
        const uint32_t bA = sb + AOFFS(buf) + aoff;
        const uint32_t bB = sb + BOFFS(buf) + boff;

        #pragma unroll
        for (int s = 0; s < 4; s++) {
            const uint32_t cb = (uint32_t)(s * 32) + lb4;
            const uint32_t cA = cb ^ maskA, cB = cb ^ maskA;  // same lane mask for A and B
            uint32_t a[4][4], b[4][4];
            #pragma unroll
            for (int mi = 0; mi < 4; mi++) ldm4(a[mi], bA + mi * 2048 + cA);
            #pragma unroll
            for (int j2 = 0; j2 < 4; j2++) ldm4(b[j2], bB + j2 * 2048 + cB);
            #pragma unroll
            for (int mi = 0; mi < 4; mi++)
                #pragma unroll
                for (int nj = 0; nj < 8; nj++) {
                    const int j2 = nj >> 1, p = nj & 1;
                    mma_f16(acc[mi][nj], a[mi], b[j2][p], b[j2][2 + p]);
                }
        }
    }

    // ---- epilogue ----
    const int rbase = m0 + wm * 64 + (lane >> 2);
    const int cbase = n0 + wn * 64 + (lane & 3) * 2;
    #pragma unroll
    for (int mi = 0; mi < 4; mi++) {
        #pragma unroll
        for (int gr = 0; gr < 2; gr++) {
            const int m = rbase + mi * 16 + gr * 8;
            float zin = 1.0f;
            if (EPI == EP_CTX) zin = 1.0f / Zv[(size_t)bz * SEQ + m];
            #pragma unroll
            for (int nj = 0; nj < 8; nj++) {
                const int col = cbase + nj * 8;
                float v0 = acc[mi][nj][gr * 2];
                float v1 = acc[mi][nj][gr * 2 + 1];
                if (EPI == EP_Q || EPI == EP_KT || EPI == EP_VT || EPI == EP_OUT) {
                    v0 += bias[col]; v1 += bias[col + 1];
                }
                if (EPI == EP_Q || EPI == EP_KT) {
                    v0 = v0 > 0.0f ? v0 + 1.0f : expf(v0);
                    v1 = v1 > 0.0f ? v1 + 1.0f : expf(v1);
                }
                if (EPI == EP_CTX) { v0 *= zin; v1 *= zin; }

                if (EPI == EP_OUT) {
                    float* o = (float*)Oh;
                    *(float2*)(o + (size_t)m * DIM + col) = make_float2(v0, v1);
                } else {
                    __half h0 = __float2half_rn(v0), h1 = __float2half_rn(v1);
                    __half* oh = (__half*)Oh;
                    if (EPI == EP_Q) {
                        *(__half2*)(oh + (size_t)m * DIM + col) = __half2{h0, h1};
                    } else if (EPI == EP_CTX) {
                        *(__half2*)(oh + ((size_t)bz * SEQ + m) * DIM + col) = __half2{h0, h1};
                    } else if (EPI == EP_KT || EPI == EP_VT) {
                        // transposed store [b][chan][seq]
                        const int b = m >> 12, nl = m & 4095;
                        const size_t a0 = (size_t)b * DIM * SEQ + (size_t)col * SEQ + nl;
                        oh[a0] = h0; oh[a0 + SEQ] = h1;
                    } else { // EP_KV: store KV^T[b][e][d], m = d contiguous
                        const size_t a0 = (size_t)bz * DIM * DIM + (size_t)col * DIM + m;
                        oh[a0] = h0; oh[a0 + DIM] = h1;
                    }
                }
            }
        }
    }
}

// ============================ launch ============================
extern "C" void kernel_launch(void* const* d_in, const int* in_sizes, int n_in,
                              void* d_out, int out_size)
{
    const float* x  = (const float*)d_in[0];
    const float* Wq = (const float*)d_in[1];
    const float* bq = (const float*)d_in[2];
    const float* Wk = (const float*)d_in[3];
    const float* bk = (const float*)d_in[4];
    const float* Wv = (const float*)d_in[5];
    const float* bv = (const float*)d_in[6];
    const float* Wo = (const float*)d_in[7];
    const float* bo = (const float*)d_in[8];

    cudaFuncSetAttribute(mm_f16<EP_Q>,   cudaFuncAttributeMaxDynamicSharedMemorySize, SMEM_BYTES);
    cudaFuncSetAttribute(mm_f16<EP_KT>,  cudaFuncAttributeMaxDynamicSharedMemorySize, SMEM_BYTES);
    cudaFuncSetAttribute(mm_f16<EP_VT>,  cudaFuncAttributeMaxDynamicSharedMemorySize, SMEM_BYTES);
    cudaFuncSetAttribute(mm_f16<EP_KV>,  cudaFuncAttributeMaxDynamicSharedMemorySize, SMEM_BYTES);
    cudaFuncSetAttribute(mm_f16<EP_CTX>, cudaFuncAttributeMaxDynamicSharedMemorySize, SMEM_BYTES);
    cudaFuncSetAttribute(mm_f16<EP_OUT>, cudaFuncAttributeMaxDynamicSharedMemorySize, SMEM_BYTES);

    __half *xh, *Qh, *Kth, *Vth, *KVth, *Wqh, *Wkh, *Wvh, *Woh;
    float *Ks, *Z;
    cudaGetSymbolAddress((void**)&xh,   g_xh);
    cudaGetSymbolAddress((void**)&Qh,   g_Qh);
    cudaGetSymbolAddress((void**)&Kth,  g_Kth);
    cudaGetSymbolAddress((void**)&Vth,  g_Vth);
    cudaGetSymbolAddress((void**)&KVth, g_KVth);
    cudaGetSymbolAddress((void**)&Wqh,  g_Wqh);
    cudaGetSymbolAddress((void**)&Wkh,  g_Wkh);
    cudaGetSymbolAddress((void**)&Wvh,  g_Wvh);
    cudaGetSymbolAddress((void**)&Woh,  g_Woh);
    cudaGetSymbolAddress((void**)&Ks,   g_Ksum);
    cudaGetSymbolAddress((void**)&Z,    g_Z);

    split1_kernel<<<2048, 256>>>((const float4*)x,  (__half2*)xh,  NROWS*DIM/4);
    split1_kernel<<<512,  256>>>((const float4*)Wq, (__half2*)Wqh, DIM*DIM/4);
    split1_kernel<<<512,  256>>>((const float4*)Wk, (__half2*)Wkh, DIM*DIM/4);
    split1_kernel<<<512,  256>>>((const float4*)Wv, (__half2*)Wvh, DIM*DIM/4);
    split1_kernel<<<512,  256>>>((const float4*)Wo, (__half2*)Woh, DIM*DIM/4);

    const dim3 thr(256);
    const dim3 gProj(DIM/256, NROWS/128, 1);

    mm_f16<EP_Q> <<<gProj, thr, SMEM_BYTES>>>(xh, Wqh, DIM, 0, 0, bq, nullptr, Qh);
    mm_f16<EP_KT><<<gProj, thr, SMEM_BYTES>>>(xh, Wkh, DIM, 0, 0, bk, nullptr, Kth);
    mm_f16<EP_VT><<<gProj, thr, SMEM_BYTES>>>(xh, Wvh, DIM, 0, 0, bv, nullptr, Vth);

    ksum_kernel<<<BATCH*DIM/8, 256>>>((const __half2*)Kth, Ks);
    z_kernel<<<NROWS/8, 256>>>((const __half2*)Qh, Ks, Z);

    // KV^T[b][e][d] = sum_n Kt[b][d][n] * Vt[b][e][n]
    const dim3 gKV(DIM/256, DIM/128, BATCH);
    mm_f16<EP_KV><<<gKV, thr, SMEM_BYTES>>>(Kth, Vth, SEQ,
                                            (size_t)DIM*SEQ, (size_t)DIM*SEQ,
                                            nullptr, nullptr, KVth);

    // ctx[b][n][e] = (Q[b][n][:] . KVt[b][e][:]) / Z  — overwrites Kt (dead)
    __half* CTX = Kth;
    const dim3 gCtx(DIM/256, SEQ/128, BATCH);
    mm_f16<EP_CTX><<<gCtx, thr, SMEM_BYTES>>>(Qh, KVth, DIM,
                                              (size_t)SEQ*DIM, (size_t)DIM*DIM,
                                              nullptr, Z, CTX);

    mm_f16<EP_OUT><<<gProj, thr, SMEM_BYTES>>>(CTX, Woh, DIM, 0, 0, bo, nullptr, d_out);
}